// round 2
// baseline (speedup 1.0000x reference)
#include <cuda_runtime.h>
#include <cuda_bf16.h>

#define NB 32
#define HW 16384
#define SPEC 3

// Per-b precomputed data: initial state vector (U0|00>) and 3 ansatz-block unitaries.
__device__ float2 g_vinit[NB][4];
__device__ float2 g_U[NB][SPEC][4][4];   // [b][i][row][col]

__device__ __forceinline__ float2 cmul(float2 a, float2 b) {
    return make_float2(fmaf(a.x, b.x, -a.y * b.y), fmaf(a.x, b.y, a.y * b.x));
}
__device__ __forceinline__ float2 cadd(float2 a, float2 b) {
    return make_float2(a.x + b.x, a.y + b.y);
}
__device__ __forceinline__ float2 cfma(float2 a, float2 b, float2 acc) {
    acc.x = fmaf(a.x, b.x, acc.x);
    acc.x = fmaf(-a.y, b.y, acc.x);
    acc.y = fmaf(a.x, b.y, acc.y);
    acc.y = fmaf(a.y, b.x, acc.y);
    return acc;
}

// ---------------------------------------------------------------------------
// Precompute kernel: one thread per (b, spectrum-slot s in 0..3).
// Builds the 4x4 unitary of the ansatz block (2 layers of [U3(w0), U3(w1), CNOT]).
// s==0 -> store only column 0 (v_init = U|00>); s>0 -> store full matrix.
// ---------------------------------------------------------------------------
__global__ void qprep_kernel(const float* __restrict__ qs) {
    int t = blockIdx.x * blockDim.x + threadIdx.x;
    if (t >= NB * 4) return;
    int b = t >> 2;
    int s = t & 3;

    float2 M[4][4];
#pragma unroll
    for (int r = 0; r < 4; r++)
#pragma unroll
        for (int c = 0; c < 4; c++)
            M[r][c] = make_float2((r == c) ? 1.0f : 0.0f, 0.0f);

#pragma unroll
    for (int j = 0; j < 2; j++) {           // ANSATZ layers
#pragma unroll
        for (int k = 0; k < 2; k++) {       // wires
            const float* p = qs + ((((b * 4 + s) * 2 + j) * 2 + k) * 3);
            float th = p[0], ph = p[1], la = p[2];
            float ct = cosf(th * 0.5f);
            float st = sinf(th * 0.5f);
            float sl, cl, sp, cp;
            sincosf(la, &sl, &cl);
            sincosf(ph, &sp, &cp);
            // U3 = [[ct, -e^{i la} st], [e^{i ph} st, e^{i(ph+la)} ct]]
            float2 g00 = make_float2(ct, 0.0f);
            float2 g01 = make_float2(-cl * st, -sl * st);
            float2 g10 = make_float2(cp * st, sp * st);
            float2 epl = cmul(make_float2(cp, sp), make_float2(cl, sl));
            float2 g11 = make_float2(epl.x * ct, epl.y * ct);

            if (k == 0) {
                // gate on wire 0 (MSB): row pairs (0,2) and (1,3)
#pragma unroll
                for (int c = 0; c < 4; c++) {
                    float2 a0 = M[0][c], a1 = M[2][c];
                    M[0][c] = cadd(cmul(g00, a0), cmul(g01, a1));
                    M[2][c] = cadd(cmul(g10, a0), cmul(g11, a1));
                    float2 b0 = M[1][c], b1 = M[3][c];
                    M[1][c] = cadd(cmul(g00, b0), cmul(g01, b1));
                    M[3][c] = cadd(cmul(g10, b0), cmul(g11, b1));
                }
            } else {
                // gate on wire 1 (LSB): row pairs (0,1) and (2,3)
#pragma unroll
                for (int c = 0; c < 4; c++) {
                    float2 a0 = M[0][c], a1 = M[1][c];
                    M[0][c] = cadd(cmul(g00, a0), cmul(g01, a1));
                    M[1][c] = cadd(cmul(g10, a0), cmul(g11, a1));
                    float2 b0 = M[2][c], b1 = M[3][c];
                    M[2][c] = cadd(cmul(g00, b0), cmul(g01, b1));
                    M[3][c] = cadd(cmul(g10, b0), cmul(g11, b1));
                }
            }
        }
        // CNOT (ctrl = wire0/MSB): swap rows 2 and 3
#pragma unroll
        for (int c = 0; c < 4; c++) {
            float2 tmp = M[2][c];
            M[2][c] = M[3][c];
            M[3][c] = tmp;
        }
    }

    if (s == 0) {
#pragma unroll
        for (int r = 0; r < 4; r++) g_vinit[b][r] = M[r][0];
    } else {
#pragma unroll
        for (int r = 0; r < 4; r++)
#pragma unroll
            for (int c = 0; c < 4; c++)
                g_U[b][s - 1][r][c] = M[r][c];
    }
}

// ---------------------------------------------------------------------------
// Main kernel: one thread per pixel. Block = one b, one chunk of hw.
// ---------------------------------------------------------------------------
__global__ void __launch_bounds__(256, 8)
qmain_kernel(const float* __restrict__ x, float* __restrict__ out) {
    const int b = blockIdx.y;
    const int h = blockIdx.x * blockDim.x + threadIdx.x;

    __shared__ float2 sV[4];
    __shared__ float2 sU[SPEC][4][4];

    int t = threadIdx.x;
    if (t < 4) sV[t] = g_vinit[b][t];
    if (t < SPEC * 16) ((float2*)sU)[t] = ((const float2*)&g_U[b][0][0][0])[t];
    __syncthreads();

    // x layout: (b, hw, 2) contiguous -> float2 at index b*HW + h
    float2 xv = reinterpret_cast<const float2*>(x)[b * HW + h];

    float s0, c0, s1, c1;
    __sincosf(xv.x, &s0, &c0);
    __sincosf(xv.y, &s1, &c1);
    // Global phase factored: diag(1, e^{i x1}, e^{i x0}, e^{i(x0+x1)})
    float2 e0 = make_float2(c0, s0);
    float2 e1 = make_float2(c1, s1);
    float2 e01 = cmul(e0, e1);

    float2 v0 = sV[0], v1 = sV[1], v2 = sV[2], v3 = sV[3];

#pragma unroll
    for (int i = 0; i < SPEC; i++) {
        // RZ diagonal (up to global phase)
        v1 = cmul(v1, e1);
        v2 = cmul(v2, e0);
        v3 = cmul(v3, e01);
        // 4x4 complex matvec: v <- U_i v
        float2 n0 = cmul(sU[i][0][0], v0);
        n0 = cfma(sU[i][0][1], v1, n0);
        n0 = cfma(sU[i][0][2], v2, n0);
        n0 = cfma(sU[i][0][3], v3, n0);
        float2 n1 = cmul(sU[i][1][0], v0);
        n1 = cfma(sU[i][1][1], v1, n1);
        n1 = cfma(sU[i][1][2], v2, n1);
        n1 = cfma(sU[i][1][3], v3, n1);
        float2 n2 = cmul(sU[i][2][0], v0);
        n2 = cfma(sU[i][2][1], v1, n2);
        n2 = cfma(sU[i][2][2], v2, n2);
        n2 = cfma(sU[i][2][3], v3, n2);
        float2 n3 = cmul(sU[i][3][0], v0);
        n3 = cfma(sU[i][3][1], v1, n3);
        n3 = cfma(sU[i][3][2], v2, n3);
        n3 = cfma(sU[i][3][3], v3, n3);
        v0 = n0; v1 = n1; v2 = n2; v3 = n3;
    }

    float ev = v0.x * v0.x + v0.y * v0.y
             + v1.x * v1.x + v1.y * v1.y
             - v2.x * v2.x - v2.y * v2.y
             - v3.x * v3.x - v3.y * v3.y;

    out[b * HW + h] = ev;
}

extern "C" void kernel_launch(void* const* d_in, const int* in_sizes, int n_in,
                              void* d_out, int out_size) {
    const float* x  = (const float*)d_in[0];   // (32, 16384, 2) float32
    const float* qs = (const float*)d_in[1];   // (32, 4, 2, 2, 3) float32
    float* out = (float*)d_out;                // (32, 16384) float32

    qprep_kernel<<<1, 128>>>(qs);

    dim3 grid(HW / 256, NB);
    qmain_kernel<<<grid, 256>>>(x, out);
}